// round 9
// baseline (speedup 1.0000x reference)
#include <cuda_runtime.h>

// MaxAssigner2D, fused:
//   Main kernel: each block owns an 8-row strip of one image.
//     Phase A: channel-max of strip into smem (coalesced LDG.128, 8 lanes/px,
//              shfl-xor reduce); boundary rows (top2/bottom2) also saved to gmem.
//     Phase B: 7-tap stencil for interior rows h0+2..h0+7 straight from smem.
//   Cleanup kernel: stencils rows h0, h0+1 of every strip from the save buffer.
// taps: {(0,0),(-1,0),(-2,0),(0,-1),(0,-2),(-1,-1),(-2,-2)}, out-of-image = 0.

#define BATCH 16
#define HGT   512
#define WID   512
#define CH    32
#define NPIX  (BATCH * HGT * WID)

#define SROWS   8                     // strip rows
#define NSTRIPS (BATCH * HGT / SROWS) // 1024
#define SPX     (SROWS * WID)         // 4096 pixels per strip
#define DATA0   4
#define SW      520                   // smem row stride (floats), 16B-aligned
#define NT      256
#define NQUAD   (WID / 4)             // 128

// save buffer: per strip, xc rows {h0, h0+1, h0+6, h0+7} (4 x 512 floats) = 8MB
__device__ float g_save[NSTRIPS * 4 * WID];

__global__ void __launch_bounds__(NT)
fused_kernel(const float* __restrict__ x, float* __restrict__ out)
{
    __shared__ float s[SROWS * SW];   // 16,640 B

    const int t    = threadIdx.x;
    const int b    = blockIdx.x;          // strip id
    const int img  = b >> 6;
    const int h0   = (b & 63) * SROWS;

    // zero left-halo cols (DATA0-2, DATA0-1) for all 8 rows
    if (t < SROWS * 2) s[(t >> 1) * SW + 2 + (t & 1)] = 0.0f;

    const int g   = t >> 3;               // pixel-group lane (0..31)
    const int chq = t & 7;                 // float4 within 32 channels
    const float* xb = x + ((size_t)img * HGT + h0) * WID * CH;
    float* saveb = g_save + (size_t)b * 4 * WID;

    // ---- Phase A: channel-max of 4096 strip pixels (128 rounds of 32 px) ----
    #pragma unroll 8
    for (int rnd = 0; rnd < SPX / 32; rnd++) {
        const int idx = rnd * 32 + g;          // pixel within strip
        const int row = idx >> 9;
        const int col = idx & 511;
        const float4 d = __ldg((const float4*)(xb + (size_t)idx * CH) + chq);
        float v = fmaxf(fmaxf(d.x, d.y), fmaxf(d.z, d.w));
        v = fmaxf(v, __shfl_xor_sync(0xffffffffu, v, 1));
        v = fmaxf(v, __shfl_xor_sync(0xffffffffu, v, 2));
        v = fmaxf(v, __shfl_xor_sync(0xffffffffu, v, 4));
        if (chq == 0) {
            s[row * SW + DATA0 + col] = v;
            if (row < 2)       saveb[row * WID + col] = v;           // slots 0,1
            else if (row >= 6) saveb[(row - 4) * WID + col] = v;     // slots 2,3
        }
    }
    __syncthreads();

    // ---- Phase B: stencil interior rows h0+2..h0+7 (768 quads, 3/thread) ----
    float4* oimg = (float4*)(out + ((size_t)img * HGT + h0) * WID);
    #pragma unroll
    for (int i = 0; i < 3; i++) {
        const int qq = i * NT + t;        // 0..767
        const int r  = 2 + (qq >> 7);     // 2..7  (= row h)
        const int q  = qq & 127;
        const float* pA = s + r * SW + DATA0 + 4 * q;       // row h
        const float* pB = pA - SW;                          // row h-1
        const float* pC = pB - SW;                          // row h-2
        const float4 a = *(const float4*)pA;
        const float4 bb = *(const float4*)pB;
        const float4 c = *(const float4*)pC;
        const float la1 = pA[-1], la2 = pA[-2];
        const float lb1 = pB[-1];
        const float lc1 = pC[-1], lc2 = pC[-2];

        float4 m;   // out(h) = max(M0(h), M1(h-1), M2(h-2))
        m.x = fmaxf(fmaxf(fmaxf(a.x, la1), fmaxf(la2, bb.x)),
                    fmaxf(lb1,  fmaxf(c.x, lc2)));
        m.y = fmaxf(fmaxf(fmaxf(a.y, a.x), fmaxf(la1, bb.y)),
                    fmaxf(bb.x, fmaxf(c.y, lc1)));
        m.z = fmaxf(fmaxf(fmaxf(a.z, a.y), fmaxf(a.x, bb.z)),
                    fmaxf(bb.y, fmaxf(c.z, c.x)));
        m.w = fmaxf(fmaxf(fmaxf(a.w, a.z), fmaxf(a.y, bb.w)),
                    fmaxf(bb.z, fmaxf(c.w, c.y)));
        oimg[(size_t)r * NQUAD + q] = m;
    }
}

// ---- Cleanup: rows h0, h0+1 of every strip from the save buffer ------------
#define CK_BLOCKS (NSTRIPS * 2 * NQUAD / NT)   // 1024

__global__ void __launch_bounds__(NT)
cleanup_kernel(float* __restrict__ out)
{
    const int u     = blockIdx.x * NT + threadIdx.x;
    const int strip = u >> 8;
    const int rr    = (u >> 7) & 1;     // 0 or 1 (row h0+rr)
    const int q     = u & 127;
    const int img   = strip >> 6;
    const int sidx  = strip & 63;
    const int h0    = sidx * SROWS;
    const bool hasPrev = (sidx != 0);

    const float* cur  = g_save + (size_t)strip * 4 * WID;
    const float* prev2 = cur - 4 * WID + 2 * WID;   // prev strip slot 2 (row h0-2)
    const float* prev3 = prev2 + WID;               // prev strip slot 3 (row h0-1)

    // rows: A = h, B = h-1, C = h-2
    const float* A = cur + rr * WID;
    const float* B = rr ? cur : prev3;
    const float* C = rr ? prev3 : prev2;
    const bool bOK = rr ? true : hasPrev;
    const bool cOK = hasPrev;

    const float4 z4 = make_float4(0.f, 0.f, 0.f, 0.f);
    const float2 z2 = make_float2(0.f, 0.f);

    const float4 a  = __ldg((const float4*)A + q);
    const float2 la = q ? __ldg((const float2*)(A + 4 * q - 2)) : z2;
    const float4 bb = bOK ? __ldg((const float4*)B + q) : z4;
    const float lb1 = (bOK && q) ? __ldg(B + 4 * q - 1) : 0.f;
    const float4 c  = cOK ? __ldg((const float4*)C + q) : z4;
    const float2 lc = (cOK && q) ? __ldg((const float2*)(C + 4 * q - 2)) : z2;

    float4 m;
    m.x = fmaxf(fmaxf(fmaxf(a.x, la.y), fmaxf(la.x, bb.x)),
                fmaxf(lb1,  fmaxf(c.x, lc.x)));
    m.y = fmaxf(fmaxf(fmaxf(a.y, a.x), fmaxf(la.y, bb.y)),
                fmaxf(bb.x, fmaxf(c.y, lc.y)));
    m.z = fmaxf(fmaxf(fmaxf(a.z, a.y), fmaxf(a.x, bb.z)),
                fmaxf(bb.y, fmaxf(c.z, c.x)));
    m.w = fmaxf(fmaxf(fmaxf(a.w, a.z), fmaxf(a.y, bb.w)),
                fmaxf(bb.z, fmaxf(c.w, c.y)));

    ((float4*)out)[((size_t)img * HGT + h0 + rr) * NQUAD + q] = m;
}

extern "C" void kernel_launch(void* const* d_in, const int* in_sizes, int n_in,
                              void* d_out, int out_size)
{
    (void)in_sizes; (void)n_in; (void)out_size;
    const float* x = (const float*)d_in[0];
    float* out = (float*)d_out;

    fused_kernel<<<NSTRIPS, NT>>>(x, out);
    cleanup_kernel<<<CK_BLOCKS, NT>>>(out);
}

// round 10
// speedup vs baseline: 1.0989x; 1.0989x over previous
#include <cuda_runtime.h>

// MaxAssigner2D, two-phase (best-known structure, R7/R8 lineage):
//   Phase 1 (streaming): xc[p] = max over 32 channels of x[p*32 .. p*32+31]
//       - explicit 8-deep load batching for guaranteed MLP
//   Phase 2 (stencil):   out[b,h,w] = max over taps
//       {(0,0),(-1,0),(-2,0),(0,-1),(0,-2),(-1,-1),(-2,-2)} of xc[b,h+dh,w+dw]
//   (out-of-image taps contribute 0, matching the reference zero pad)

#define BATCH 16
#define HGT   512
#define WID   512
#define CH    32
#define NPIX  (BATCH * HGT * WID)   // 4,194,304

__device__ float g_xc[NPIX];        // 16 MB scratch (allocation-free)

// ---------------- Phase 1: channel-max, batched streaming -------------------
// 8 lanes per pixel: one coalesced LDG.128 each (512B contiguous per warp).
// 8 loads are issued back-to-back into a register array (MLP=8/thread),
// then all shfl-reduces and stores drain. Exact trip counts throughout.
#define K1_NT      256
#define K1_BLOCKS  2048
#define K1_GROUPS  (K1_BLOCKS * K1_NT / 8)        // 65,536 pixel groups / sweep
#define K1_ITERS   (NPIX / K1_GROUPS)             // 64, exact
#define K1_B       8                               // load batch depth
#define K1_OUTER   (K1_ITERS / K1_B)               // 8

__global__ void __launch_bounds__(K1_NT)
chanmax_kernel(const float* __restrict__ x)
{
    const int tid = blockIdx.x * K1_NT + threadIdx.x;
    const int gid = tid >> 3;           // pixel-group id
    const int chq = tid & 7;            // which float4 of 32 channels

    const float4* src0 = (const float4*)(x + (size_t)gid * CH) + chq;

    for (int o = 0; o < K1_OUTER; o++) {
        float4 d[K1_B];
        // front-batched independent loads: 8 x LDG.128 with no consumers between
        #pragma unroll
        for (int j = 0; j < K1_B; j++) {
            const size_t p = (size_t)(o * K1_B + j) * K1_GROUPS;
            d[j] = __ldg(src0 + p * (CH / 4));
        }
        // drain: reduce + cross-lane + predicated store
        #pragma unroll
        for (int j = 0; j < K1_B; j++) {
            float v = fmaxf(fmaxf(d[j].x, d[j].y), fmaxf(d[j].z, d[j].w));
            v = fmaxf(v, __shfl_xor_sync(0xffffffffu, v, 1));
            v = fmaxf(v, __shfl_xor_sync(0xffffffffu, v, 2));
            v = fmaxf(v, __shfl_xor_sync(0xffffffffu, v, 4));
            if (chq == 0) g_xc[(o * K1_B + j) * K1_GROUPS + gid] = v;
        }
    }
}

// ---------------- Phase 2: direct-load 7-tap stencil (R7, best: 7.84us) ----
#define K2_NT     256
#define K2_BLOCKS (NPIX / 4 / K2_NT)    // 4096

__global__ void __launch_bounds__(K2_NT)
stencil_kernel(const float* __restrict__ xc, float* __restrict__ out)
{
    const int p   = blockIdx.x * K2_NT + threadIdx.x;  // quad id
    const int q   = p & 127;            // quad within row (cols 4q..4q+3)
    const int h   = (p >> 7) & 511;     // image row

    const float* base = xc + ((size_t)p << 2);   // &xc[img][h][4q]

    // Row h: always valid.
    const float4 a2 = __ldg((const float4*)base);
    float2 l2 = make_float2(0.f, 0.f);           // cols 4q-2, 4q-1 of row h
    if (q) l2 = __ldg((const float2*)(base - 2));

    // Rows h-1, h-2: may be above the image (zero pad).
    float4 a1 = make_float4(0.f, 0.f, 0.f, 0.f);
    float4 a0 = make_float4(0.f, 0.f, 0.f, 0.f);
    float  l1 = 0.f;                             // col 4q-1 of row h-1
    float2 l0 = make_float2(0.f, 0.f);           // cols 4q-2, 4q-1 of row h-2
    if (h >= 1) {
        a1 = __ldg((const float4*)(base - WID));
        if (q) l1 = __ldg(base - WID - 1);
    }
    if (h >= 2) {
        a0 = __ldg((const float4*)(base - 2 * WID));
        if (q) l0 = __ldg((const float2*)(base - 2 * WID - 2));
    }

    // taps per output col j: (0,j)(0,j-1)(0,j-2) | (-1,j)(-1,j-1) | (-2,j)(-2,j-2)
    float4 m;
    m.x = fmaxf(fmaxf(fmaxf(a2.x, l2.y), fmaxf(l2.x, a1.x)),
                fmaxf(l1,   fmaxf(a0.x, l0.x)));
    m.y = fmaxf(fmaxf(fmaxf(a2.y, a2.x), fmaxf(l2.y, a1.y)),
                fmaxf(a1.x, fmaxf(a0.y, l0.y)));
    m.z = fmaxf(fmaxf(fmaxf(a2.z, a2.y), fmaxf(a2.x, a1.z)),
                fmaxf(a1.y, fmaxf(a0.z, a0.x)));
    m.w = fmaxf(fmaxf(fmaxf(a2.w, a2.z), fmaxf(a2.y, a1.w)),
                fmaxf(a1.z, fmaxf(a0.w, a0.y)));

    ((float4*)out)[p] = m;
}

extern "C" void kernel_launch(void* const* d_in, const int* in_sizes, int n_in,
                              void* d_out, int out_size)
{
    (void)in_sizes; (void)n_in; (void)out_size;
    const float* x = (const float*)d_in[0];
    float* out = (float*)d_out;

    float* xc_ptr;
    cudaGetSymbolAddress((void**)&xc_ptr, g_xc);

    chanmax_kernel<<<K1_BLOCKS, K1_NT>>>(x);
    stencil_kernel<<<K2_BLOCKS, K2_NT>>>(xc_ptr, out);
}